// round 13
// baseline (speedup 1.0000x reference)
#include <cuda_runtime.h>

#define NG 8
#define NT 2048
#define NH 2048
#define NE 8
#define CAP 320

#define NTOK (NG * NT)                 // 16384
#define OFF_PMAX   (NTOK * NE)         // 131072
#define OFF_LOGITS (OFF_PMAX + NTOK)   // 147456

#define TPW 4                          // tokens per warp
#define THREADS 256                    // 8 warps -> 32 tokens per block
#define BLOCKS (NTOK / (TPW * 8))      // 512
#define BPG (BLOCKS / NG)              // 64 blocks per group

typedef unsigned long long u64;

__device__ int g_expert_id[NTOK];
__device__ unsigned g_ctr[NG];         // monotone across graph replays

__device__ __forceinline__ u64 pack2(float a, float b) {
    u64 r;
    asm("mov.b64 %0, {%1, %2};" : "=l"(r) : "f"(a), "f"(b));
    return r;
}
__device__ __forceinline__ u64 dup2(float a) {
    u64 r;
    asm("mov.b64 %0, {%1, %1};" : "=l"(r) : "f"(a));
    return r;
}
__device__ __forceinline__ void unpack2(u64 v, float& a, float& b) {
    asm("mov.b64 {%0, %1}, %2;" : "=f"(a), "=f"(b) : "l"(v));
}
__device__ __forceinline__ void fma2(u64& d, u64 a, u64 b) {
    asm("fma.rn.f32x2 %0, %1, %2, %0;" : "+l"(d) : "l"(a), "l"(b));
}
__device__ __forceinline__ u64 add2(u64 a, u64 b) {
    u64 r;
    asm("add.rn.f32x2 %0, %1, %2;" : "=l"(r) : "l"(a), "l"(b));
    return r;
}

// W in smem, [h][expert-pair] order, expert-paired u64, 16B-chunk swizzled:
// logical u64 index u = h*4 + ep holds (W[2ep][h], W[2ep+1][h]).
// physical u64 index = (u>>9)*512 + ((u>>4)&31)*16
//                      + ((((u>>1)&7) + ((u>>4)&31)) & 7)*2 + (u&1)
extern __shared__ u64 sWp[];           // 8192 u64 = 64KB

__global__ void __launch_bounds__(THREADS, 3)
router_fused_kernel(const float* __restrict__ hs,
                    const float* __restrict__ W,
                    const float* __restrict__ bias,
                    float* __restrict__ out) {
    const int tid  = threadIdx.x;
    const int lane = tid & 31;
    const int t0   = ((blockIdx.x * THREADS + tid) >> 5) * TPW;

    const float4* __restrict__ xb = (const float4*)hs + (size_t)t0 * (NH / 4);

    // stage W (expert-paired, swizzled) into shared memory
    for (int u = tid; u < 4 * NH; u += THREADS) {        // 32 per thread
        const int h = u >> 2, ep = u & 3;
        const float a = __ldg(W + (2 * ep) * NH + h);
        const float b = __ldg(W + (2 * ep + 1) * NH + h);
        const int row = u >> 9;
        const int ln  = (u >> 4) & 31;
        const int c   = (u >> 1) & 7;
        const int phys = row * 512 + ln * 16 + (((c + ln) & 7) << 1) + (u & 1);
        sWp[phys] = pack2(a, b);
    }
    __syncthreads();

    // acc[tok][ep] = f32x2 (expert 2ep, expert 2ep+1). 32 registers.
    u64 acc[TPW][4];
#pragma unroll
    for (int k = 0; k < TPW; ++k)
#pragma unroll
        for (int ep = 0; ep < 4; ++ep) acc[k][ep] = 0ull;

    // lane's physical W row base (bytes): it*4096 + lane*128; chunk c at
    // + ((c+lane)&7)*16
    const char* __restrict__ wb = (const char*)sWp + lane * 128;

#pragma unroll 2
    for (int it = 0; it < NH / (32 * 4); ++it) {         // 16 iterations
        // x: one float4 per token, h = (it*32+lane)*4 .. +3
        float4 x[TPW];
#pragma unroll
        for (int k = 0; k < TPW; ++k)
            x[k] = __ldg(xb + k * (NH / 4) + it * 32 + lane);

        const char* __restrict__ wrow = wb + it * 4096;
#pragma unroll
        for (int j = 0; j < 4; ++j) {                    // h offset within float4
            const int c01 = ((2 * j + 0) + lane) & 7;
            const int c23 = ((2 * j + 1) + lane) & 7;
            const ulonglong2 e01 = *(const ulonglong2*)(wrow + c01 * 16);
            const ulonglong2 e23 = *(const ulonglong2*)(wrow + c23 * 16);
#pragma unroll
            for (int k = 0; k < TPW; ++k) {
                const u64 xd = dup2((&x[k].x)[j]);
                fma2(acc[k][0], xd, e01.x);
                fma2(acc[k][1], xd, e01.y);
                fma2(acc[k][2], xd, e23.x);
                fma2(acc[k][3], xd, e23.y);
            }
        }
    }

    // packed butterfly reduction: 16 u64 values over 32 lanes.
    // After 4 steps + xor-1, lane L holds value idx16=(L>>1)&15 = tok*4+ep.
    u64 r[16];
#pragma unroll
    for (int k = 0; k < TPW; ++k)
#pragma unroll
        for (int ep = 0; ep < 4; ++ep) r[k * 4 + ep] = acc[k][ep];

#pragma unroll
    for (int s = 0; s < 4; ++s) {
        const int off  = 16 >> s;
        const int half = 8 >> s;
        const int sel  = (lane >> (4 - s)) & 1;
#pragma unroll
        for (int i = 0; i < half; ++i) {
            const u64 a = r[i];
            const u64 b = r[half + i];
            const u64 mine = sel ? b : a;
            const u64 send = sel ? a : b;
            const u64 recv = __shfl_xor_sync(0xffffffffu, send, off);
            r[i] = add2(mine, recv);
        }
    }
    r[0] = add2(r[0], __shfl_xor_sync(0xffffffffu, r[0], 1));

    const int idx16 = (lane >> 1) & 15;
    const int tok = idx16 >> 2;
    const int ep  = idx16 & 3;
    const int t   = t0 + tok;

    const float2 bb = __ldg((const float2*)bias + ep);
    const u64 l64 = add2(r[0], pack2(bb.x, bb.y));
    float lo, hi;
    unpack2(l64, lo, hi);

    // fully coalesced logits store: float index t0*8 + lane (128B per warp)
    out[OFF_LOGITS + (size_t)t0 * NE + lane] = (lane & 1) ? hi : lo;

    // max/argmax (first-max tie-break) + softmax denom across ep lanes
    const int e0 = 2 * ep;
    float mx;
    int am;
    if (hi > lo) { mx = hi; am = e0 + 1; } else { mx = lo; am = e0; }
#pragma unroll
    for (int off = 2; off <= 4; off <<= 1) {
        const float omx = __shfl_xor_sync(0xffffffffu, mx, off);
        const int   oam = __shfl_xor_sync(0xffffffffu, am, off);
        if (omx > mx || (omx == mx && oam < am)) { mx = omx; am = oam; }
    }
    float s = __expf(lo - mx) + __expf(hi - mx);
    s += __shfl_xor_sync(0xffffffffu, s, 2);
    s += __shfl_xor_sync(0xffffffffu, s, 4);

    if ((lane & 7) == 0) {             // ep==0 && bit0==0; tok = lane>>3
        out[OFF_PMAX + t] = 1.0f / s;
        g_expert_id[t] = am;
    }

    // ----------------- fused capacity scan (last block of group) ------------
    __shared__ int s_g;
    __syncthreads();
    if (tid == 0) {
        __threadfence();                          // release our id writes
        const int grp = (int)(blockIdx.x / BPG);
        const unsigned old = atomicAdd(&g_ctr[grp], 1u);
        s_g = (((old + 1u) & (BPG - 1u)) == 0u) ? grp : -1;
    }
    __syncthreads();
    const int g = s_g;
    if (g < 0) return;
    __threadfence();                              // acquire all id writes

    const int4* __restrict__ ids4 = (const int4*)(g_expert_id + g * NT);

    int myid[8];                                  // 2048 / 256 threads
    u64 c0 = 0ull, c1 = 0ull;
#pragma unroll
    for (int q = 0; q < 2; ++q) {
        const int4 rr = ids4[tid * 2 + q];
        myid[q * 4 + 0] = rr.x; myid[q * 4 + 1] = rr.y;
        myid[q * 4 + 2] = rr.z; myid[q * 4 + 3] = rr.w;
    }
#pragma unroll
    for (int i = 0; i < 8; ++i) {
        const int ee = myid[i];
        if (ee < 4) c0 += 1ull << (ee * 16);
        else        c1 += 1ull << ((ee - 4) * 16);
    }

    __shared__ u64 sA[THREADS], sB[THREADS];
    u64 i0 = c0, i1 = c1;
    sA[tid] = i0; sB[tid] = i1;
    __syncthreads();
#pragma unroll
    for (int off = 1; off < THREADS; off <<= 1) {
        u64 a = 0ull, b = 0ull;
        if (tid >= off) { a = sA[tid - off]; b = sB[tid - off]; }
        __syncthreads();
        i0 += a; i1 += b;
        sA[tid] = i0; sB[tid] = i1;
        __syncthreads();
    }
    u64 r0 = i0 - c0, r1 = i1 - c1;               // exclusive prefix

    __shared__ unsigned char sflag[NT];           // eid (3b) | keep (bit 3)
#pragma unroll
    for (int i = 0; i < 8; ++i) {
        const int ee = myid[i];
        int prio;
        if (ee < 4) { r0 += 1ull << (ee * 16);       prio = (int)((r0 >> (ee * 16)) & 0xFFFF); }
        else        { r1 += 1ull << ((ee - 4) * 16); prio = (int)((r1 >> ((ee - 4) * 16)) & 0xFFFF); }
        sflag[tid * 8 + i] = (unsigned char)(ee | ((prio <= CAP) ? 8 : 0));
    }
    __syncthreads();

    // coalesced one-hot write: 256 threads write consecutive float4
    float4* __restrict__ dst = (float4*)out + (size_t)g * NT * 2;
    for (int k = tid; k < NT * 2; k += THREADS) {
        const int fl   = sflag[k >> 1];
        const int ee   = fl & 7;
        const float kp = (fl & 8) ? 1.0f : 0.0f;
        const int rel  = ee - (k & 1) * 4;
        float4 v4 = make_float4(0.f, 0.f, 0.f, 0.f);
        if (rel >= 0 && rel < 4) (&v4.x)[rel] = kp;
        dst[k] = v4;
    }
}

extern "C" void kernel_launch(void* const* d_in, const int* in_sizes, int n_in,
                              void* d_out, int out_size) {
    const float* hs   = (const float*)d_in[0];
    const float* W    = (const float*)d_in[1];
    const float* bias = (const float*)d_in[2];
    float* out = (float*)d_out;

    static const int SMEM = 4 * NH * (int)sizeof(u64);   // 64KB dynamic
    cudaFuncSetAttribute(router_fused_kernel,
                         cudaFuncAttributeMaxDynamicSharedMemorySize, SMEM);
    router_fused_kernel<<<BLOCKS, THREADS, SMEM>>>(hs, W, bias, out);
}

// round 14
// speedup vs baseline: 1.0266x; 1.0266x over previous
#include <cuda_runtime.h>

#define NG 8
#define NT 2048
#define NH 2048
#define NE 8
#define CAP 320

#define NTOK (NG * NT)                 // 16384
#define OFF_PMAX   (NTOK * NE)         // 131072
#define OFF_LOGITS (OFF_PMAX + NTOK)   // 147456

#define TPW 4                          // tokens per warp
#define THREADS 256                    // 8 warps -> 32 tokens per block
#define BLOCKS (NTOK / (TPW * 8))      // 512
#define BPG (BLOCKS / NG)              // 64 blocks per group

typedef unsigned long long u64;

__device__ int g_expert_id[NTOK];
__device__ unsigned g_ctr[NG];         // monotone across graph replays

__device__ __forceinline__ u64 pack2(float a, float b) {
    u64 r;
    asm("mov.b64 %0, {%1, %2};" : "=l"(r) : "f"(a), "f"(b));
    return r;
}
__device__ __forceinline__ u64 dup2(float a) {
    u64 r;
    asm("mov.b64 %0, {%1, %1};" : "=l"(r) : "f"(a));
    return r;
}
__device__ __forceinline__ void unpack2(u64 v, float& a, float& b) {
    asm("mov.b64 {%0, %1}, %2;" : "=f"(a), "=f"(b) : "l"(v));
}
__device__ __forceinline__ void fma2(u64& d, u64 a, u64 b) {
    asm("fma.rn.f32x2 %0, %1, %2, %0;" : "+l"(d) : "l"(a), "l"(b));
}
__device__ __forceinline__ u64 add2(u64 a, u64 b) {
    u64 r;
    asm("add.rn.f32x2 %0, %1, %2;" : "=l"(r) : "l"(a), "l"(b));
    return r;
}

// W in smem, [h][expert-pair] order, expert-paired u64, 16B-chunk swizzled:
// logical u64 index u = h*4 + ep holds (W[2ep][h], W[2ep+1][h]).
// physical u64 index = (u>>9)*512 + ((u>>4)&31)*16
//                      + ((((u>>1)&7) + ((u>>4)&31)) & 7)*2 + (u&1)
extern __shared__ u64 sWp[];           // 8192 u64 = 64KB

__global__ void __launch_bounds__(THREADS, 3)
router_fused_kernel(const float* __restrict__ hs,
                    const float* __restrict__ W,
                    const float* __restrict__ bias,
                    float* __restrict__ out) {
    const int tid  = threadIdx.x;
    const int lane = tid & 31;
    const int t0   = ((blockIdx.x * THREADS + tid) >> 5) * TPW;

    const float4* __restrict__ xb = (const float4*)hs + (size_t)t0 * (NH / 4);

    // stage W (expert-paired, swizzled) into shared memory
    for (int u = tid; u < 4 * NH; u += THREADS) {        // 32 per thread
        const int h = u >> 2, ep = u & 3;
        const float a = __ldg(W + (2 * ep) * NH + h);
        const float b = __ldg(W + (2 * ep + 1) * NH + h);
        const int row = u >> 9;
        const int ln  = (u >> 4) & 31;
        const int c   = (u >> 1) & 7;
        const int phys = row * 512 + ln * 16 + (((c + ln) & 7) << 1) + (u & 1);
        sWp[phys] = pack2(a, b);
    }
    __syncthreads();

    // acc[tok][ep] = f32x2 (expert 2ep, expert 2ep+1). 32 registers.
    u64 acc[TPW][4];
#pragma unroll
    for (int k = 0; k < TPW; ++k)
#pragma unroll
        for (int ep = 0; ep < 4; ++ep) acc[k][ep] = 0ull;

    // lane's physical W row base (bytes): it*4096 + lane*128; chunk c at
    // + ((c+lane)&7)*16
    const char* __restrict__ wb = (const char*)sWp + lane * 128;

#pragma unroll 2
    for (int it = 0; it < NH / (32 * 4); ++it) {         // 16 iterations
        // x: one float4 per token, h = (it*32+lane)*4 .. +3
        float4 x[TPW];
#pragma unroll
        for (int k = 0; k < TPW; ++k)
            x[k] = __ldg(xb + k * (NH / 4) + it * 32 + lane);

        const char* __restrict__ wrow = wb + it * 4096;
#pragma unroll
        for (int j = 0; j < 4; ++j) {                    // h offset within float4
            const int c01 = ((2 * j + 0) + lane) & 7;
            const int c23 = ((2 * j + 1) + lane) & 7;
            const ulonglong2 e01 = *(const ulonglong2*)(wrow + c01 * 16);
            const ulonglong2 e23 = *(const ulonglong2*)(wrow + c23 * 16);
#pragma unroll
            for (int k = 0; k < TPW; ++k) {
                const u64 xd = dup2((&x[k].x)[j]);
                fma2(acc[k][0], xd, e01.x);
                fma2(acc[k][1], xd, e01.y);
                fma2(acc[k][2], xd, e23.x);
                fma2(acc[k][3], xd, e23.y);
            }
        }
    }

    // packed butterfly reduction: 16 u64 values over 32 lanes.
    // After 4 steps + xor-1, lane L holds value idx16=(L>>1)&15 = tok*4+ep.
    u64 r[16];
#pragma unroll
    for (int k = 0; k < TPW; ++k)
#pragma unroll
        for (int ep = 0; ep < 4; ++ep) r[k * 4 + ep] = acc[k][ep];

#pragma unroll
    for (int s = 0; s < 4; ++s) {
        const int off  = 16 >> s;
        const int half = 8 >> s;
        const int sel  = (lane >> (4 - s)) & 1;
#pragma unroll
        for (int i = 0; i < half; ++i) {
            const u64 a = r[i];
            const u64 b = r[half + i];
            const u64 mine = sel ? b : a;
            const u64 send = sel ? a : b;
            const u64 recv = __shfl_xor_sync(0xffffffffu, send, off);
            r[i] = add2(mine, recv);
        }
    }
    r[0] = add2(r[0], __shfl_xor_sync(0xffffffffu, r[0], 1));

    const int idx16 = (lane >> 1) & 15;
    const int tok = idx16 >> 2;
    const int ep  = idx16 & 3;
    const int t   = t0 + tok;

    const float2 bb = __ldg((const float2*)bias + ep);
    const u64 l64 = add2(r[0], pack2(bb.x, bb.y));
    float lo, hi;
    unpack2(l64, lo, hi);

    // fully coalesced logits store: float index t0*8 + lane (128B per warp)
    out[OFF_LOGITS + (size_t)t0 * NE + lane] = (lane & 1) ? hi : lo;

    // max/argmax (first-max tie-break) + softmax denom across ep lanes
    const int e0 = 2 * ep;
    float mx;
    int am;
    if (hi > lo) { mx = hi; am = e0 + 1; } else { mx = lo; am = e0; }
#pragma unroll
    for (int off = 2; off <= 4; off <<= 1) {
        const float omx = __shfl_xor_sync(0xffffffffu, mx, off);
        const int   oam = __shfl_xor_sync(0xffffffffu, am, off);
        if (omx > mx || (omx == mx && oam < am)) { mx = omx; am = oam; }
    }
    float s = __expf(lo - mx) + __expf(hi - mx);
    s += __shfl_xor_sync(0xffffffffu, s, 2);
    s += __shfl_xor_sync(0xffffffffu, s, 4);

    if ((lane & 7) == 0) {             // ep==0 && bit0==0; tok = lane>>3
        out[OFF_PMAX + t] = 1.0f / s;
        g_expert_id[t] = am;
    }

    // ----------------- fused capacity scan (last block of group) ------------
    __shared__ int s_g;
    __syncthreads();
    if (tid == 0) {
        __threadfence();                          // release our id writes
        const int grp = (int)(blockIdx.x / BPG);
        const unsigned old = atomicAdd(&g_ctr[grp], 1u);
        s_g = (((old + 1u) & (BPG - 1u)) == 0u) ? grp : -1;
    }
    __syncthreads();
    const int g = s_g;
    if (g < 0) return;
    __threadfence();                              // acquire all id writes

    const int4* __restrict__ ids4 = (const int4*)(g_expert_id + g * NT);

    int myid[8];                                  // 2048 / 256 threads
    u64 c0 = 0ull, c1 = 0ull;
#pragma unroll
    for (int q = 0; q < 2; ++q) {
        const int4 rr = ids4[tid * 2 + q];
        myid[q * 4 + 0] = rr.x; myid[q * 4 + 1] = rr.y;
        myid[q * 4 + 2] = rr.z; myid[q * 4 + 3] = rr.w;
    }
#pragma unroll
    for (int i = 0; i < 8; ++i) {
        const int ee = myid[i];
        if (ee < 4) c0 += 1ull << (ee * 16);
        else        c1 += 1ull << ((ee - 4) * 16);
    }

    __shared__ u64 sA[THREADS], sB[THREADS];
    u64 i0 = c0, i1 = c1;
    sA[tid] = i0; sB[tid] = i1;
    __syncthreads();
#pragma unroll
    for (int off = 1; off < THREADS; off <<= 1) {
        u64 a = 0ull, b = 0ull;
        if (tid >= off) { a = sA[tid - off]; b = sB[tid - off]; }
        __syncthreads();
        i0 += a; i1 += b;
        sA[tid] = i0; sB[tid] = i1;
        __syncthreads();
    }
    u64 r0 = i0 - c0, r1 = i1 - c1;               // exclusive prefix

    __shared__ unsigned char sflag[NT];           // eid (3b) | keep (bit 3)
#pragma unroll
    for (int i = 0; i < 8; ++i) {
        const int ee = myid[i];
        int prio;
        if (ee < 4) { r0 += 1ull << (ee * 16);       prio = (int)((r0 >> (ee * 16)) & 0xFFFF); }
        else        { r1 += 1ull << ((ee - 4) * 16); prio = (int)((r1 >> ((ee - 4) * 16)) & 0xFFFF); }
        sflag[tid * 8 + i] = (unsigned char)(ee | ((prio <= CAP) ? 8 : 0));
    }
    __syncthreads();

    // coalesced one-hot write: 256 threads write consecutive float4
    float4* __restrict__ dst = (float4*)out + (size_t)g * NT * 2;
    for (int k = tid; k < NT * 2; k += THREADS) {
        const int fl   = sflag[k >> 1];
        const int ee   = fl & 7;
        const float kp = (fl & 8) ? 1.0f : 0.0f;
        const int rel  = ee - (k & 1) * 4;
        float4 v4 = make_float4(0.f, 0.f, 0.f, 0.f);
        if (rel >= 0 && rel < 4) (&v4.x)[rel] = kp;
        dst[k] = v4;
    }
}

extern "C" void kernel_launch(void* const* d_in, const int* in_sizes, int n_in,
                              void* d_out, int out_size) {
    const float* hs   = (const float*)d_in[0];
    const float* W    = (const float*)d_in[1];
    const float* bias = (const float*)d_in[2];
    float* out = (float*)d_out;

    static const int SMEM = 4 * NH * (int)sizeof(u64);   // 64KB dynamic
    cudaFuncSetAttribute(router_fused_kernel,
                         cudaFuncAttributeMaxDynamicSharedMemorySize, SMEM);
    router_fused_kernel<<<BLOCKS, THREADS, SMEM>>>(hs, W, bias, out);
}

// round 16
// speedup vs baseline: 1.2730x; 1.2400x over previous
#include <cuda_runtime.h>

#define NG 8
#define NT 2048
#define NH 2048
#define NE 8
#define CAP 320

#define NTOK (NG * NT)                 // 16384
#define OFF_PMAX   (NTOK * NE)         // 131072
#define OFF_LOGITS (OFF_PMAX + NTOK)   // 147456

#define TPW 4                          // tokens per warp
#define THREADS 256                    // 8 warps -> 32 tokens per tile
#define TILES (NTOK / 32)              // 512
#define BLOCKS (TILES * 2)             // 1024 (2 H-halves per tile)
#define TPG 64                         // tiles per group

typedef unsigned long long u64;

__device__ float    g_part[BLOCKS * 256];   // per-block partial logits (1MB)
__device__ int      g_expert_id[NTOK];
__device__ unsigned g_tile_ctr[TILES];      // +2 per launch (monotone)
__device__ unsigned g_ctr[NG];              // +64 per launch (monotone)

__device__ __forceinline__ u64 pack2(float a, float b) {
    u64 r;
    asm("mov.b64 %0, {%1, %2};" : "=l"(r) : "f"(a), "f"(b));
    return r;
}
__device__ __forceinline__ void unpack2(u64 v, float& a, float& b) {
    asm("mov.b64 {%0, %1}, %2;" : "=f"(a), "=f"(b) : "l"(v));
}
__device__ __forceinline__ void fma2(u64& d, u64 a, u64 b) {
    asm("fma.rn.f32x2 %0, %1, %2, %0;" : "+l"(d) : "l"(a), "l"(b));
}

extern __shared__ float4 sW[];         // [NE][NH/8] float4 = 2048 f4 = 32KB

__global__ void __launch_bounds__(THREADS, 2)
router_fused_kernel(const float* __restrict__ hs,
                    const float* __restrict__ W,
                    const float* __restrict__ bias,
                    float* __restrict__ out) {
    const int tid  = threadIdx.x;
    const int lane = tid & 31;
    const int tile = blockIdx.x >> 1;
    const int half = blockIdx.x & 1;
    const int t0w  = tile * 32 + (tid >> 5) * TPW;        // warp's 4 tokens

    // x: this block covers H-half [half*1024, +1024) of each of its tokens
    const float4* __restrict__ xb =
        (const float4*)hs + (size_t)t0w * (NH / 4) + half * (NH / 8);

    // stage this half's W slice: sW[e][c] = W[e][half*1024 + c*4 ..]
    {
        const float4* __restrict__ wv = (const float4*)W;
#pragma unroll
        for (int k = 0; k < NE; ++k)                      // e = k
            sW[k * (NH / 8) + tid] =
                __ldg(wv + k * (NH / 4) + half * (NH / 8) + tid);
    }
    __syncthreads();

    // acc[tok][e], f32x2 packed along H. 64 registers. (R4 body, 8 iters)
    u64 acc[TPW][NE];
#pragma unroll
    for (int tk = 0; tk < TPW; ++tk)
#pragma unroll
        for (int e = 0; e < NE; ++e) acc[tk][e] = 0ull;

#pragma unroll 2
    for (int it = 0; it < NH / (32 * 8); ++it) {          // 8 iterations
        const int idx = it * 32 + lane;
        u64 xlo[TPW], xhi[TPW];
#pragma unroll
        for (int k = 0; k < TPW; ++k) {
            const float4 x = __ldg(xb + k * (NH / 4) + idx);
            xlo[k] = pack2(x.x, x.y);
            xhi[k] = pack2(x.z, x.w);
        }
#pragma unroll
        for (int e = 0; e < NE; ++e) {
            const float4 w = sW[e * (NH / 8) + idx];
            const u64 wlo = pack2(w.x, w.y);
            const u64 whi = pack2(w.z, w.w);
#pragma unroll
            for (int k = 0; k < TPW; ++k) {
                fma2(acc[k][e], xlo[k], wlo);
                fma2(acc[k][e], xhi[k], whi);
            }
        }
    }

    // v[t*8+e]: 32 partial sums per lane
    float v[32];
#pragma unroll
    for (int tk = 0; tk < TPW; ++tk)
#pragma unroll
        for (int e = 0; e < NE; ++e) {
            float a, b;
            unpack2(acc[tk][e], a, b);
            v[tk * 8 + e] = a + b;
        }

    // 5-step butterfly: lane L ends with total for value L (tok L>>3, e L&7)
#pragma unroll
    for (int s = 0; s < 5; ++s) {
        const int off  = 16 >> s;
        const int half2 = 16 >> s;
        const int sel  = (lane >> (4 - s)) & 1;
#pragma unroll
        for (int i = 0; i < half2; ++i) {
            const float a = v[i];
            const float b = v[half2 + i];
            const float mine = sel ? b : a;
            const float send = sel ? a : b;
            const float recv = __shfl_xor_sync(0xffffffffu, send, off);
            v[i] = mine + recv;
        }
    }

    // store this half's partial: slot = tid within block (warp*32+lane)
    g_part[(size_t)blockIdx.x * 256 + tid] = v[0];

    // ---------------- tile combine (second finisher of the pair) -----------
    __shared__ int s_fin;
    __syncthreads();                    // all g_part stores done (HB for fence)
    if (tid == 0) {
        __threadfence();                // release partials
        const unsigned old = atomicAdd(&g_tile_ctr[tile], 1u);
        s_fin = (((old + 1u) & 1u) == 0u) ? 1 : 0;
    }
    __syncthreads();
    if (!s_fin) return;
    __threadfence();                    // acquire sibling's partials

    {
        const int i = tid;              // value index within tile: tok*8+e
        const float p = g_part[(size_t)(tile * 2) * 256 + i] +
                        g_part[(size_t)(tile * 2 + 1) * 256 + i];
        const int e = i & 7;
        const int t = tile * 32 + (i >> 3);
        const float l = p + __ldg(bias + e);

        // coalesced logits store (256 consecutive floats per block)
        out[OFF_LOGITS + (size_t)tile * 256 + i] = l;

        // max/argmax (first-max tie-break) + softmax denom in 8-lane groups
        float mx = l;
        int am = e;
#pragma unroll
        for (int off = 1; off <= 4; off <<= 1) {
            const float omx = __shfl_xor_sync(0xffffffffu, mx, off);
            const int   oam = __shfl_xor_sync(0xffffffffu, am, off);
            if (omx > mx || (omx == mx && oam < am)) { mx = omx; am = oam; }
        }
        float s = __expf(l - mx);
#pragma unroll
        for (int off = 1; off <= 4; off <<= 1)
            s += __shfl_xor_sync(0xffffffffu, s, off);

        if (e == 0) {
            out[OFF_PMAX + t] = 1.0f / s;
            g_expert_id[t] = am;
        }
    }

    // ----------------- capacity scan (last tile of group) ------------------
    __shared__ int s_g;
    __syncthreads();                    // g_expert_id writes done
    if (tid == 0) {
        __threadfence();                // release our id writes
        const int grp = tile / TPG;
        const unsigned old = atomicAdd(&g_ctr[grp], 1u);
        s_g = (((old + 1u) & (TPG - 1u)) == 0u) ? grp : -1;
    }
    __syncthreads();
    const int g = s_g;
    if (g < 0) return;
    __threadfence();                    // acquire all id writes

    const int4* __restrict__ ids4 = (const int4*)(g_expert_id + g * NT);

    int myid[8];                        // 2048 / 256 threads
    u64 c0 = 0ull, c1 = 0ull;
#pragma unroll
    for (int q = 0; q < 2; ++q) {
        const int4 rr = ids4[tid * 2 + q];
        myid[q * 4 + 0] = rr.x; myid[q * 4 + 1] = rr.y;
        myid[q * 4 + 2] = rr.z; myid[q * 4 + 3] = rr.w;
    }
#pragma unroll
    for (int i = 0; i < 8; ++i) {
        const int ee = myid[i];
        if (ee < 4) c0 += 1ull << (ee * 16);
        else        c1 += 1ull << ((ee - 4) * 16);
    }

    __shared__ u64 sA[THREADS], sB[THREADS];
    u64 i0 = c0, i1 = c1;
    sA[tid] = i0; sB[tid] = i1;
    __syncthreads();
#pragma unroll
    for (int off = 1; off < THREADS; off <<= 1) {
        u64 a = 0ull, b = 0ull;
        if (tid >= off) { a = sA[tid - off]; b = sB[tid - off]; }
        __syncthreads();
        i0 += a; i1 += b;
        sA[tid] = i0; sB[tid] = i1;
        __syncthreads();
    }
    u64 r0 = i0 - c0, r1 = i1 - c1;     // exclusive prefix

    __shared__ unsigned char sflag[NT]; // eid (3b) | keep (bit 3)
#pragma unroll
    for (int i = 0; i < 8; ++i) {
        const int ee = myid[i];
        int prio;
        if (ee < 4) { r0 += 1ull << (ee * 16);       prio = (int)((r0 >> (ee * 16)) & 0xFFFF); }
        else        { r1 += 1ull << ((ee - 4) * 16); prio = (int)((r1 >> ((ee - 4) * 16)) & 0xFFFF); }
        sflag[tid * 8 + i] = (unsigned char)(ee | ((prio <= CAP) ? 8 : 0));
    }
    __syncthreads();

    // coalesced one-hot write: 256 threads write consecutive float4
    float4* __restrict__ dst = (float4*)out + (size_t)g * NT * 2;
    for (int k = tid; k < NT * 2; k += THREADS) {
        const int fl   = sflag[k >> 1];
        const int ee   = fl & 7;
        const float kp = (fl & 8) ? 1.0f : 0.0f;
        const int rel  = ee - (k & 1) * 4;
        float4 v4 = make_float4(0.f, 0.f, 0.f, 0.f);
        if (rel >= 0 && rel < 4) (&v4.x)[rel] = kp;
        dst[k] = v4;
    }
}

extern "C" void kernel_launch(void* const* d_in, const int* in_sizes, int n_in,
                              void* d_out, int out_size) {
    const float* hs   = (const float*)d_in[0];
    const float* W    = (const float*)d_in[1];
    const float* bias = (const float*)d_in[2];
    float* out = (float*)d_out;

    static const int SMEM = NE * (NH / 2) * (int)sizeof(float);  // 32KB dynamic
    cudaFuncSetAttribute(router_fused_kernel,
                         cudaFuncAttributeMaxDynamicSharedMemorySize, SMEM);
    router_fused_kernel<<<BLOCKS, THREADS, SMEM>>>(hs, W, bias, out);
}